// round 16
// baseline (speedup 1.0000x reference)
#include <cuda_runtime.h>
#include <cuda_fp16.h>
#include <mma.h>
#include <math.h>

using namespace nvcuda;

#define B_ 8
#define N_ 4096
#define D_ 1024
#define H_ 8
#define NTOK 4097   // 1 cls + 4096 feat tokens
#define BH_ 4       // batches per pipeline half

// ---------------- scratch (static device allocations only) ----------------
__device__ unsigned long long g_best[B_];     // packed (score_key << 32) | ~idx
__device__ int    g_tick[B_];                 // score completion tickets (self-resetting)
__device__ float  g_Q[B_*D_];
__device__ float  g_Qp[B_*D_];
__device__ float  g_u[B_*H_*D_];
__device__ __half g_u16[B_*D_*16];            // u fp16, [b][d][16 head-pad]; heads 8-15 stay 0
__device__ __half g_x[(size_t)B_*N_*D_];      // post relu+conv features, fp16
__device__ float  g_logits[B_*H_*NTOK];
__device__ __half g_A16[(size_t)B_*16*4096];  // softmax weights fp16; rows 8-15 stay 0
__device__ float  g_xbar[B_*16*D_];           // [b][16 head-pad][d]
__device__ float  g_O[B_*D_];

__device__ __forceinline__ float warp_sum(float v){
    #pragma unroll
    for (int o = 16; o; o >>= 1) v += __shfl_xor_sync(0xffffffffu, v, o);
    return v;
}

// load float2 (2 channels), relu(v - q) in half2
__device__ __forceinline__ __half2 ld_relu2(const float* p, __half2 q){
    float2 v = *(const float2*)p;
    return __hmax2(__hsub2(__floats2half2_rn(v.x, v.y), q), __float2half2_rn(0.f));
}

// ---------------- 1) score + fused argmax + g_u zero + Q copy ----------------
__global__ void k_score(const float* __restrict__ inp, const float* __restrict__ wenc){
    int gw   = blockIdx.x*8 + (threadIdx.x >> 5);
    int lane = threadIdx.x & 31;
    int b    = blockIdx.x >> 9;                      // 512 blocks per batch

    if (threadIdx.x < 4)
        ((float4*)g_u)[blockIdx.x*4 + threadIdx.x] = make_float4(0.f,0.f,0.f,0.f);

    const float4* row = (const float4*)(inp + (size_t)gw * D_);
    const float4* wp  = (const float4*)wenc;
    float acc = 0.f;
    #pragma unroll
    for (int j = 0; j < 8; j++){
        float4 x = row[j*32 + lane];
        float4 w = __ldg(&wp[j*32 + lane]);
        acc += x.x*w.x + x.y*w.y + x.z*w.z + x.w*w.w;
    }
    acc = warp_sum(acc);
    __shared__ unsigned long long sbest[8];
    if (lane == 0){
        unsigned int fb  = __float_as_uint(acc);
        unsigned int key = (fb & 0x80000000u) ? ~fb : (fb | 0x80000000u);
        unsigned int n   = (unsigned int)(gw & (N_-1));
        sbest[threadIdx.x >> 5] = ((unsigned long long)key << 32) | (unsigned long long)(~n);
    }
    __syncthreads();
    __shared__ int slast;
    if (threadIdx.x == 0){
        unsigned long long m = sbest[0];
        #pragma unroll
        for (int i = 1; i < 8; i++) m = (sbest[i] > m) ? sbest[i] : m;
        atomicMax(&g_best[b], m);
        __threadfence();
        slast = (atomicAdd(&g_tick[b], 1) == 511);
    }
    __syncthreads();
    if (slast){
        __threadfence();
        unsigned int n = (~(unsigned int)(g_best[b] & 0xffffffffull)) & (N_-1);
        const float4* src = (const float4*)(inp + ((size_t)b*N_ + n) * D_);
        float4* dq = (float4*)(g_Q + b*D_);
        dq[threadIdx.x] = src[threadIdx.x];
        if (threadIdx.x == 0) g_tick[b] = 0;     // reset for next replay
    }
}

// ---------------- 2) Qp: block per output row j ----------------
__global__ void __launch_bounds__(256) k_qp(const float* __restrict__ Wq, const float* __restrict__ bq){
    int j = blockIdx.x, t = threadIdx.x, lane = t & 31, wp = t >> 5;
    float4 w = __ldg((const float4*)(Wq + (size_t)j * D_) + t);
    float acc[B_];
    #pragma unroll
    for (int b = 0; b < B_; b++){
        float4 q = __ldg((const float4*)(g_Q + b*D_) + t);
        acc[b] = w.x*q.x + w.y*q.y + w.z*q.z + w.w*q.w;
    }
    __shared__ float red[8][B_];
    #pragma unroll
    for (int b = 0; b < B_; b++) acc[b] = warp_sum(acc[b]);
    if (lane == 0){
        #pragma unroll
        for (int b = 0; b < B_; b++) red[wp][b] = acc[b];
    }
    __syncthreads();
    if (t < B_){
        float s = 0.f;
        #pragma unroll
        for (int i = 0; i < 8; i++) s += red[i][t];
        g_Qp[t*D_ + j] = s + bq[j];
    }
}

// ---------------- 3) u[b,h,i] += partial (grid (16,H,4), atomic accumulate) ----------------
__global__ void __launch_bounds__(256) k_u(const float* __restrict__ Wk){
    int h  = blockIdx.y, jc = blockIdx.z;
    int il = threadIdx.x & 63;
    int js = threadIdx.x >> 6;

    __shared__ float qp[B_][32];
    { int t = threadIdx.x;
      qp[t >> 5][t & 31] = g_Qp[(t >> 5)*D_ + h*128 + jc*32 + (t & 31)]; }
    __syncthreads();

    int i = blockIdx.x*64 + il;
    const float* wkp = Wk + (size_t)(h*128 + jc*32 + js*8) * D_ + i;
    float acc[B_];
    #pragma unroll
    for (int b = 0; b < B_; b++) acc[b] = 0.f;
    #pragma unroll
    for (int j = 0; j < 8; j++){
        float w = wkp[(size_t)j * D_];
        #pragma unroll
        for (int b = 0; b < B_; b++) acc[b] += qp[b][js*8 + j] * w;
    }

    __shared__ float part[4][64][B_];
    #pragma unroll
    for (int b = 0; b < B_; b++) part[js][il][b] = acc[b];
    __syncthreads();

    for (int idx = threadIdx.x; idx < 64*B_; idx += 256){
        int ii = idx >> 3, b = idx & 7;
        float s = part[0][ii][b] + part[1][ii][b] + part[2][ii][b] + part[3][ii][b];
        atomicAdd(&g_u[((size_t)(b*H_ + h))*D_ + blockIdx.x*64 + ii], s);
    }
}

// ---------------- 4) u -> fp16 transpose [b][d][16]; heads 8..15 remain 0 ----------------
__global__ void k_u16(){
    int idx = blockIdx.x*256 + threadIdx.x;
    int b = idx >> 10, d = idx & 1023;
    __half h8[8];
    #pragma unroll
    for (int h = 0; h < 8; h++)
        h8[h] = __float2half(g_u[(((size_t)(b*H_ + h)) << 10) | d]);
    __half* dst = g_u16 + (size_t)idx * 16;
    *(uint4*)dst = *(uint4*)h8;
    *(uint4*)(dst + 8) = make_uint4(0,0,0,0);
}

// ---------------- 5) conv (HALF: 4 batches from b0): relu + dw3x3 + residual -> g_x ----------------
__global__ void __launch_bounds__(256, 4) k_conv(const float* __restrict__ inp,
                                                 const float* __restrict__ convw,
                                                 const float* __restrict__ convb,
                                                 int b0){
    int b  = b0 + blockIdx.z;
    int cg = threadIdx.x & 31;
    int tr = threadIdx.x >> 5;
    int c0 = blockIdx.x*64 + cg*2;
    int h0 = blockIdx.y*16 + tr*2;

    const float* base = inp + (size_t)b*N_*D_ + c0;
    float2 qf = *(const float2*)(g_Q + b*D_ + c0);
    __half2 q  = __floats2half2_rn(qf.x, qf.y);
    float2 cf = *(const float2*)(convb + c0);
    __half2 cb = __floats2half2_rn(cf.x, cf.y);

    __half2 wgt[9];
    #pragma unroll
    for (int k = 0; k < 9; k++)
        wgt[k] = __floats2half2_rn(convw[(c0+0)*9 + k], convw[(c0+1)*9 + k]);

    bool vld[4];
    const float* rp[4];
    #pragma unroll
    for (int r = 0; r < 4; r++){
        int hh = h0 - 1 + r;
        vld[r] = (hh >= 0) && (hh < 64);
        int hc = hh < 0 ? 0 : (hh > 63 ? 63 : hh);
        rp[r] = base + (size_t)(hc*64) * D_;
    }

    __half2 Z = __float2half2_rn(0.f);
    __half2 L[4], C[4], R[4];
    #pragma unroll
    for (int r = 0; r < 4; r++){
        L[r] = Z;
        C[r] = vld[r] ? ld_relu2(rp[r], q) : Z;
    }

    __half* out0 = g_x + ((size_t)b*N_ + h0*64) * D_ + c0;
    __half* out1 = out0 + (size_t)64 * D_;
    #pragma unroll 4
    for (int w = 0; w < 64; w++){
        #pragma unroll
        for (int r = 0; r < 4; r++)
            R[r] = (w < 63 && vld[r]) ? ld_relu2(rp[r] + (size_t)(w+1) * D_, q) : Z;

        __half2 a0 = cb, a1 = cb;
        #pragma unroll
        for (int r = 0; r < 3; r++){
            a0 = __hfma2(wgt[r*3+0], L[r],   a0);
            a0 = __hfma2(wgt[r*3+1], C[r],   a0);
            a0 = __hfma2(wgt[r*3+2], R[r],   a0);
            a1 = __hfma2(wgt[r*3+0], L[r+1], a1);
            a1 = __hfma2(wgt[r*3+1], C[r+1], a1);
            a1 = __hfma2(wgt[r*3+2], R[r+1], a1);
        }
        *(__half2*)(out0 + (size_t)w * D_) = __hadd2(a0, C[1]);
        *(__half2*)(out1 + (size_t)w * D_) = __hadd2(a1, C[2]);
        #pragma unroll
        for (int r = 0; r < 4; r++){ L[r] = C[r]; C[r] = R[r]; }
    }
}

// ---------------- 6) logits (HALF): k-split wmma; grid (N/16, 4) ----------------
__global__ void __launch_bounds__(256) k_logits(int b0){
    int b  = b0 + blockIdx.y;
    int m0 = blockIdx.x * 16;
    int t = threadIdx.x, warp = t >> 5;

    wmma::fragment<wmma::matrix_a,16,16,16,__half,wmma::row_major> fa;
    wmma::fragment<wmma::matrix_b,16,16,16,__half,wmma::row_major> fb;
    wmma::fragment<wmma::accumulator,16,16,16,float> fc_;
    wmma::fill_fragment(fc_, 0.f);

    const __half* xr = g_x   + ((size_t)b*N_ + m0) * D_;
    const __half* ur = g_u16 + (size_t)b*D_*16;
    #pragma unroll
    for (int kk = 0; kk < 8; kk++){
        int k = warp*8 + kk;
        wmma::load_matrix_sync(fa, xr + k*16, D_);
        wmma::load_matrix_sync(fb, ur + k*16*16, 16);
        wmma::mma_sync(fc_, fa, fb, fc_);
    }
    __shared__ float part[8][256];
    wmma::store_matrix_sync(&part[warp][0], fc_, 16, wmma::mem_row_major);
    __syncthreads();

    int tok = t >> 4, hh = t & 15;
    if (hh < 8){
        float s = 0.f;
        #pragma unroll
        for (int w = 0; w < 8; w++) s += part[w][t];
        g_logits[((size_t)(b*H_ + hh))*NTOK + m0 + tok + 1] = s * 0.03125f;
    }
}

// ---------------- 7) softmax (HALF: 32 blocks) + cls logit + A16 emit + xbar cls init ----------------
__global__ void __launch_bounds__(512) k_softmax(const float* __restrict__ cls, int b0){
    int bh = b0*H_ + blockIdx.x;           // 32 blocks cover 4 batches x 8 heads
    int b = bh >> 3, h = bh & 7;
    float* lg = g_logits + (size_t)bh * NTOK;
    __shared__ float sred[16];
    __shared__ float sbc;
    int t = threadIdx.x, lane = t & 31, warp = t >> 5;

    // cls logit (k=0): dot(u[bh], cls)/32
    {
        const float* u = g_u + (size_t)bh * D_;
        float a = 0.f;
        for (int d = t; d < D_; d += 512) a += u[d] * cls[d];
        a = warp_sum(a);
        if (lane == 0) sred[warp] = a;
        __syncthreads();
        if (t == 0){
            float s = 0.f;
            #pragma unroll
            for (int i = 0; i < 16; i++) s += sred[i];
            lg[0] = s * 0.03125f;
        }
        __syncthreads();
    }

    float mx = -INFINITY;
    for (int k = t; k < NTOK; k += 512) mx = fmaxf(mx, lg[k]);
    #pragma unroll
    for (int o = 16; o; o >>= 1) mx = fmaxf(mx, __shfl_xor_sync(0xffffffffu, mx, o));
    if (lane == 0) sred[warp] = mx;
    __syncthreads();
    if (t == 0){
        float m = sred[0];
        #pragma unroll
        for (int i = 1; i < 16; i++) m = fmaxf(m, sred[i]);
        sbc = m;
    }
    __syncthreads();
    float m = sbc;

    float sum = 0.f;
    for (int k = t; k < NTOK; k += 512){
        float e = expf(lg[k] - m);
        lg[k] = e;
        sum += e;
    }
    sum = warp_sum(sum);
    if (lane == 0) sred[warp] = sum;
    __syncthreads();
    if (t == 0){
        float s = 0.f;
        #pragma unroll
        for (int i = 0; i < 16; i++) s += sred[i];
        sbc = s;
    }
    __syncthreads();
    float inv = 1.f / sbc;
    __half* arow = g_A16 + ((size_t)b*16 + h) * 4096;
    for (int k = t; k < NTOK; k += 512){
        float v = lg[k] * inv;
        lg[k] = v;
        if (k > 0) arow[k-1] = __float2half(v);
    }
    __syncthreads();

    float a0 = lg[0];
    float* xb = g_xbar + ((size_t)b*16 + h) * D_;
    for (int d = t; d < D_; d += 512)
        xb[d] = a0 * cls[d];
}

// ---------------- 8) xbar (HALF): k-split wmma, grid (4,16,4) ----------------
__global__ void __launch_bounds__(256) k_xbar(int b0){
    int b    = b0 + blockIdx.z;
    int ks   = blockIdx.y;                 // 0..15, 256 tokens each
    int warp = threadIdx.x >> 5, lane = threadIdx.x & 31;
    int nt0  = blockIdx.x*8 + warp;        // 0..31

    wmma::fragment<wmma::matrix_a,16,16,16,__half,wmma::row_major> fa;
    wmma::fragment<wmma::matrix_b,16,16,16,__half,wmma::row_major> fb0, fb1;
    wmma::fragment<wmma::accumulator,16,16,16,float> acc0, acc1;
    wmma::fill_fragment(acc0, 0.f);
    wmma::fill_fragment(acc1, 0.f);

    const __half* ar = g_A16 + (size_t)b*16*4096 + ks*256;
    const __half* xr = g_x   + ((size_t)b*N_ + ks*256) * D_;
    #pragma unroll
    for (int k = 0; k < 16; k++){
        wmma::load_matrix_sync(fa, ar + k*16, 4096);
        wmma::load_matrix_sync(fb0, xr + (size_t)k*16*D_ + nt0*16, D_);
        wmma::load_matrix_sync(fb1, xr + (size_t)k*16*D_ + (nt0+32)*16, D_);
        wmma::mma_sync(acc0, fa, fb0, acc0);
        wmma::mma_sync(acc1, fa, fb1, acc1);
    }
    __shared__ float sx[8][512];
    wmma::store_matrix_sync(&sx[warp][0],   acc0, 16, wmma::mem_row_major);
    wmma::store_matrix_sync(&sx[warp][256], acc1, 16, wmma::mem_row_major);
    __syncwarp();
    #pragma unroll
    for (int e = lane; e < 128; e += 32){       // rows 0..7 only
        int r = e >> 4, c = e & 15;
        atomicAdd(&g_xbar[((size_t)b*16 + r)*D_ + nt0*16 + c],      sx[warp][r*16 + c]);
        atomicAdd(&g_xbar[((size_t)b*16 + r)*D_ + (nt0+32)*16 + c], sx[warp][256 + r*16 + c]);
    }
}

// ---------------- 9) O: block per row j; also init out[] (block 0) ----------------
__global__ void __launch_bounds__(256) k_O(const float* __restrict__ Wv, const float* __restrict__ bv,
                                           const float* __restrict__ bfc, float* __restrict__ out){
    int j = blockIdx.x, t = threadIdx.x, lane = t & 31, wp = t >> 5;
    int h = j >> 7;
    if (j == 0 && t < 16) out[t] = bfc[t & 1];
    float4 w = __ldg((const float4*)(Wv + (size_t)j * D_) + t);
    float acc[B_];
    #pragma unroll
    for (int b = 0; b < B_; b++){
        float4 v = __ldg((const float4*)(g_xbar + ((size_t)(b*16 + h))*D_) + t);
        acc[b] = w.x*v.x + w.y*v.y + w.z*v.z + w.w*v.w;
    }
    __shared__ float red[8][B_];
    #pragma unroll
    for (int b = 0; b < B_; b++) acc[b] = warp_sum(acc[b]);
    if (lane == 0){
        #pragma unroll
        for (int b = 0; b < B_; b++) red[wp][b] = acc[b];
    }
    __syncthreads();
    if (t < B_){
        float s = 0.f;
        #pragma unroll
        for (int i = 0; i < 8; i++) s += red[i][t];
        g_O[t*D_ + j] = g_Qp[t*D_ + j] + bv[j] + s;
    }
}

// ---------------- 10) O2+fc fused: out[b,c] += (O + relu(Wo.O + bo))_j * Wfc[c,j] ----------------
__global__ void __launch_bounds__(256) k_O2F(const float* __restrict__ Wo, const float* __restrict__ bo,
                                             const float* __restrict__ Wfc, float* __restrict__ out){
    int j = blockIdx.x, t = threadIdx.x, lane = t & 31, wp = t >> 5;
    float4 w = __ldg((const float4*)(Wo + (size_t)j * D_) + t);
    float acc[B_];
    #pragma unroll
    for (int b = 0; b < B_; b++){
        float4 v = __ldg((const float4*)(g_O + (size_t)b*D_) + t);
        acc[b] = w.x*v.x + w.y*v.y + w.z*v.z + w.w*v.w;
    }
    __shared__ float red[8][B_];
    #pragma unroll
    for (int b = 0; b < B_; b++) acc[b] = warp_sum(acc[b]);
    if (lane == 0){
        #pragma unroll
        for (int b = 0; b < B_; b++) red[wp][b] = acc[b];
    }
    __syncthreads();
    if (t < B_){
        float s = 0.f;
        #pragma unroll
        for (int i = 0; i < 8; i++) s += red[i][t];
        float o2 = g_O[t*D_ + j] + fmaxf(s + bo[j], 0.f);
        atomicAdd(&out[t*2 + 0], o2 * Wfc[j]);
        atomicAdd(&out[t*2 + 1], o2 * Wfc[D_ + j]);
    }
}

// ---------------- stream/event infra (created in global ctor) ----------------
static cudaStream_t s_aux;
static cudaEvent_t  ev_q, ev_c0, ev_c1;
namespace {
struct _FRMIL_Init {
    _FRMIL_Init(){
        cudaStreamCreateWithFlags(&s_aux, cudaStreamNonBlocking);
        cudaEventCreateWithFlags(&ev_q,  cudaEventDisableTiming);
        cudaEventCreateWithFlags(&ev_c0, cudaEventDisableTiming);
        cudaEventCreateWithFlags(&ev_c1, cudaEventDisableTiming);
    }
} _frmil_init_;
}

// ---------------- launcher: 2-deep pipeline (4-batch halves) ----------------
extern "C" void kernel_launch(void* const* d_in, const int* in_sizes, int n_in,
                              void* d_out, int out_size){
    const float* inputs = (const float*)d_in[0];
    const float* Wenc   = (const float*)d_in[1];
    // d_in[2] = b_enc : constant shift through sigmoid, irrelevant for argmax
    const float* cls    = (const float*)d_in[3];
    const float* convw  = (const float*)d_in[4];
    const float* convb  = (const float*)d_in[5];
    const float* Wq     = (const float*)d_in[6];
    const float* bq     = (const float*)d_in[7];
    const float* Wk     = (const float*)d_in[8];
    // d_in[9] = bk : constant per (b,h) logit offset -> cancels in softmax
    const float* Wv     = (const float*)d_in[10];
    const float* bv     = (const float*)d_in[11];
    const float* Wo     = (const float*)d_in[12];
    const float* bo     = (const float*)d_in[13];
    const float* Wfc    = (const float*)d_in[14];
    const float* bfc    = (const float*)d_in[15];
    float* out = (float*)d_out;

    k_score<<<B_*N_/8, 256>>>(inputs, Wenc);     // score + argmax + g_u zero + Q copy
    cudaEventRecord(ev_q, 0);

    // aux: conv in two 4-batch halves
    cudaStreamWaitEvent(s_aux, ev_q, 0);
    k_conv<<<dim3(16, 4, BH_), 256, 0, s_aux>>>(inputs, convw, convb, 0);
    cudaEventRecord(ev_c0, s_aux);
    k_conv<<<dim3(16, 4, BH_), 256, 0, s_aux>>>(inputs, convw, convb, BH_);
    cudaEventRecord(ev_c1, s_aux);

    // main: small matvecs overlap conv half 0
    k_qp  <<<D_, 256>>>(Wq, bq);
    k_u   <<<dim3(16, H_, 4), 256>>>(Wk);
    k_u16 <<<32, 256>>>();

    // half 0 tail overlaps conv half 1
    cudaStreamWaitEvent(0, ev_c0, 0);
    k_logits <<<dim3(N_/16, BH_), 256>>>(0);
    k_softmax<<<BH_*H_, 512>>>(cls, 0);
    k_xbar   <<<dim3(4, 16, BH_), 256>>>(0);

    // half 1 tail
    cudaStreamWaitEvent(0, ev_c1, 0);
    k_logits <<<dim3(N_/16, BH_), 256>>>(BH_);
    k_softmax<<<BH_*H_, 512>>>(cls, BH_);
    k_xbar   <<<dim3(4, 16, BH_), 256>>>(BH_);

    k_O  <<<D_, 256>>>(Wv, bv, bfc, out);
    k_O2F<<<D_, 256>>>(Wo, bo, Wfc, out);
}

// round 17
// speedup vs baseline: 1.1584x; 1.1584x over previous
#include <cuda_runtime.h>
#include <cuda_fp16.h>
#include <mma.h>
#include <math.h>

using namespace nvcuda;

#define B_ 8
#define N_ 4096
#define D_ 1024
#define H_ 8
#define NTOK 4097   // 1 cls + 4096 feat tokens

// ---------------- scratch (static device allocations only) ----------------
__device__ unsigned long long g_best[B_];     // packed (score_key << 32) | ~idx
__device__ int    g_tick[B_];                 // score completion tickets (self-resetting)
__device__ float  g_Q[B_*D_];
__device__ float  g_Qp[B_*D_];
__device__ float  g_u[B_*H_*D_];
__device__ __half g_u16[B_*D_*16];            // u fp16, [b][d][16 head-pad]; heads 8-15 stay 0
__device__ __half g_x[(size_t)B_*N_*D_];      // post relu+conv features, fp16
__device__ float  g_logits[B_*H_*NTOK];
__device__ __half g_A16[(size_t)B_*16*4096];  // softmax weights fp16 [b][16 head-pad][tok]; rows 8-15 unused
__device__ float  g_xbar[B_*16*D_];           // [b][16 head-pad][d]
__device__ float  g_O[B_*D_];

__device__ __forceinline__ float warp_sum(float v){
    #pragma unroll
    for (int o = 16; o; o >>= 1) v += __shfl_xor_sync(0xffffffffu, v, o);
    return v;
}

// load float2 (2 channels), relu(v - q) in half2
__device__ __forceinline__ __half2 ld_relu2(const float* p, __half2 q){
    float2 v = *(const float2*)p;
    return __hmax2(__hsub2(__floats2half2_rn(v.x, v.y), q), __float2half2_rn(0.f));
}

// ---------------- 1) score + fused argmax + g_u zero + Q copy ----------------
__global__ void k_score(const float* __restrict__ inp, const float* __restrict__ wenc){
    int gw   = blockIdx.x*8 + (threadIdx.x >> 5);
    int lane = threadIdx.x & 31;
    int b    = blockIdx.x >> 9;                      // 512 blocks per batch

    if (threadIdx.x < 4)
        ((float4*)g_u)[blockIdx.x*4 + threadIdx.x] = make_float4(0.f,0.f,0.f,0.f);

    const float4* row = (const float4*)(inp + (size_t)gw * D_);
    const float4* wp  = (const float4*)wenc;
    float acc = 0.f;
    #pragma unroll
    for (int j = 0; j < 8; j++){
        float4 x = row[j*32 + lane];
        float4 w = __ldg(&wp[j*32 + lane]);
        acc += x.x*w.x + x.y*w.y + x.z*w.z + x.w*w.w;
    }
    acc = warp_sum(acc);
    __shared__ unsigned long long sbest[8];
    if (lane == 0){
        unsigned int fb  = __float_as_uint(acc);
        unsigned int key = (fb & 0x80000000u) ? ~fb : (fb | 0x80000000u);
        unsigned int n   = (unsigned int)(gw & (N_-1));
        sbest[threadIdx.x >> 5] = ((unsigned long long)key << 32) | (unsigned long long)(~n);
    }
    __syncthreads();
    __shared__ int slast;
    if (threadIdx.x == 0){
        unsigned long long m = sbest[0];
        #pragma unroll
        for (int i = 1; i < 8; i++) m = (sbest[i] > m) ? sbest[i] : m;
        atomicMax(&g_best[b], m);
        __threadfence();
        slast = (atomicAdd(&g_tick[b], 1) == 511);
    }
    __syncthreads();
    if (slast){
        __threadfence();
        unsigned int n = (~(unsigned int)(g_best[b] & 0xffffffffull)) & (N_-1);
        const float4* src = (const float4*)(inp + ((size_t)b*N_ + n) * D_);
        float4* dq = (float4*)(g_Q + b*D_);
        dq[threadIdx.x] = src[threadIdx.x];
        if (threadIdx.x == 0) g_tick[b] = 0;     // reset for next replay
    }
}

// ---------------- 2) Qp: block per output row j ----------------
__global__ void __launch_bounds__(256) k_qp(const float* __restrict__ Wq, const float* __restrict__ bq){
    int j = blockIdx.x, t = threadIdx.x, lane = t & 31, wp = t >> 5;
    float4 w = __ldg((const float4*)(Wq + (size_t)j * D_) + t);
    float acc[B_];
    #pragma unroll
    for (int b = 0; b < B_; b++){
        float4 q = __ldg((const float4*)(g_Q + b*D_) + t);
        acc[b] = w.x*q.x + w.y*q.y + w.z*q.z + w.w*q.w;
    }
    __shared__ float red[8][B_];
    #pragma unroll
    for (int b = 0; b < B_; b++) acc[b] = warp_sum(acc[b]);
    if (lane == 0){
        #pragma unroll
        for (int b = 0; b < B_; b++) red[wp][b] = acc[b];
    }
    __syncthreads();
    if (t < B_){
        float s = 0.f;
        #pragma unroll
        for (int i = 0; i < 8; i++) s += red[i][t];
        g_Qp[t*D_ + j] = s + bq[j];
    }
}

// ---------------- 3) u[b,h,i] += partial (grid (16,H,4), atomic accumulate) ----------------
__global__ void __launch_bounds__(256) k_u(const float* __restrict__ Wk){
    int h  = blockIdx.y, jc = blockIdx.z;
    int il = threadIdx.x & 63;
    int js = threadIdx.x >> 6;

    __shared__ float qp[B_][32];
    { int t = threadIdx.x;
      qp[t >> 5][t & 31] = g_Qp[(t >> 5)*D_ + h*128 + jc*32 + (t & 31)]; }
    __syncthreads();

    int i = blockIdx.x*64 + il;
    const float* wkp = Wk + (size_t)(h*128 + jc*32 + js*8) * D_ + i;
    float acc[B_];
    #pragma unroll
    for (int b = 0; b < B_; b++) acc[b] = 0.f;
    #pragma unroll
    for (int j = 0; j < 8; j++){
        float w = wkp[(size_t)j * D_];
        #pragma unroll
        for (int b = 0; b < B_; b++) acc[b] += qp[b][js*8 + j] * w;
    }

    __shared__ float part[4][64][B_];
    #pragma unroll
    for (int b = 0; b < B_; b++) part[js][il][b] = acc[b];
    __syncthreads();

    for (int idx = threadIdx.x; idx < 64*B_; idx += 256){
        int ii = idx >> 3, b = idx & 7;
        float s = part[0][ii][b] + part[1][ii][b] + part[2][ii][b] + part[3][ii][b];
        atomicAdd(&g_u[((size_t)(b*H_ + h))*D_ + blockIdx.x*64 + ii], s);
    }
}

// ---------------- 4) u -> fp16 transpose [b][d][16]; heads 8..15 remain 0 ----------------
// grid 64 x 128 (was 32 x 256): double SM coverage for this latency-bound kernel.
__global__ void __launch_bounds__(128) k_u16(){
    int idx = blockIdx.x*128 + threadIdx.x;   // 8192 (b,d) pairs
    int b = idx >> 10, d = idx & 1023;
    __half h8[8];
    #pragma unroll
    for (int h = 0; h < 8; h++)
        h8[h] = __float2half(g_u[(((size_t)(b*H_ + h)) << 10) | d]);
    __half* dst = g_u16 + (size_t)idx * 16;
    *(uint4*)dst = *(uint4*)h8;
    *(uint4*)(dst + 8) = make_uint4(0,0,0,0);
}

// ---------------- 5) relu + depthwise 3x3 conv + residual -> g_x (HFMA2, 2 rows x 2 ch) ----------------
__global__ void __launch_bounds__(256, 4) k_conv(const float* __restrict__ inp,
                                                 const float* __restrict__ convw,
                                                 const float* __restrict__ convb){
    int b  = blockIdx.z;
    int cg = threadIdx.x & 31;
    int tr = threadIdx.x >> 5;
    int c0 = blockIdx.x*64 + cg*2;
    int h0 = blockIdx.y*16 + tr*2;

    const float* base = inp + (size_t)b*N_*D_ + c0;
    float2 qf = *(const float2*)(g_Q + b*D_ + c0);
    __half2 q  = __floats2half2_rn(qf.x, qf.y);
    float2 cf = *(const float2*)(convb + c0);
    __half2 cb = __floats2half2_rn(cf.x, cf.y);

    __half2 wgt[9];
    #pragma unroll
    for (int k = 0; k < 9; k++)
        wgt[k] = __floats2half2_rn(convw[(c0+0)*9 + k], convw[(c0+1)*9 + k]);

    bool vld[4];
    const float* rp[4];
    #pragma unroll
    for (int r = 0; r < 4; r++){
        int hh = h0 - 1 + r;
        vld[r] = (hh >= 0) && (hh < 64);
        int hc = hh < 0 ? 0 : (hh > 63 ? 63 : hh);
        rp[r] = base + (size_t)(hc*64) * D_;
    }

    __half2 Z = __float2half2_rn(0.f);
    __half2 L[4], C[4], R[4];
    #pragma unroll
    for (int r = 0; r < 4; r++){
        L[r] = Z;
        C[r] = vld[r] ? ld_relu2(rp[r], q) : Z;
    }

    __half* out0 = g_x + ((size_t)b*N_ + h0*64) * D_ + c0;
    __half* out1 = out0 + (size_t)64 * D_;
    #pragma unroll 4
    for (int w = 0; w < 64; w++){
        #pragma unroll
        for (int r = 0; r < 4; r++)
            R[r] = (w < 63 && vld[r]) ? ld_relu2(rp[r] + (size_t)(w+1) * D_, q) : Z;

        __half2 a0 = cb, a1 = cb;
        #pragma unroll
        for (int r = 0; r < 3; r++){
            a0 = __hfma2(wgt[r*3+0], L[r],   a0);
            a0 = __hfma2(wgt[r*3+1], C[r],   a0);
            a0 = __hfma2(wgt[r*3+2], R[r],   a0);
            a1 = __hfma2(wgt[r*3+0], L[r+1], a1);
            a1 = __hfma2(wgt[r*3+1], C[r+1], a1);
            a1 = __hfma2(wgt[r*3+2], R[r+1], a1);
        }
        *(__half2*)(out0 + (size_t)w * D_) = __hadd2(a0, C[1]);
        *(__half2*)(out1 + (size_t)w * D_) = __hadd2(a1, C[2]);
        #pragma unroll
        for (int r = 0; r < 4; r++){ L[r] = C[r]; C[r] = R[r]; }
    }
}

// ---------------- 6) logits: k-split wmma. Block = one 16-token tile; 8 warps x 8 k-steps ----------------
__global__ void __launch_bounds__(256) k_logits(){
    int b    = blockIdx.y;
    int m0   = blockIdx.x * 16;
    int t = threadIdx.x, warp = t >> 5;

    wmma::fragment<wmma::matrix_a,16,16,16,__half,wmma::row_major> fa;
    wmma::fragment<wmma::matrix_b,16,16,16,__half,wmma::row_major> fb;
    wmma::fragment<wmma::accumulator,16,16,16,float> fc_;
    wmma::fill_fragment(fc_, 0.f);

    const __half* xr = g_x   + ((size_t)b*N_ + m0) * D_;
    const __half* ur = g_u16 + (size_t)b*D_*16;
    #pragma unroll
    for (int kk = 0; kk < 8; kk++){
        int k = warp*8 + kk;
        wmma::load_matrix_sync(fa, xr + k*16, D_);
        wmma::load_matrix_sync(fb, ur + k*16*16, 16);
        wmma::mma_sync(fc_, fa, fb, fc_);
    }
    __shared__ float part[8][256];
    wmma::store_matrix_sync(&part[warp][0], fc_, 16, wmma::mem_row_major);
    __syncthreads();

    int tok = t >> 4, hh = t & 15;
    if (hh < 8){
        float s = 0.f;
        #pragma unroll
        for (int w = 0; w < 8; w++) s += part[w][t];
        g_logits[((size_t)(b*H_ + hh))*NTOK + m0 + tok + 1] = s * 0.03125f;
    }
}

// ---------------- 7) softmax (512 threads) + cls logit inline + A16 emit + xbar cls init ----------------
__global__ void __launch_bounds__(512) k_softmax(const float* __restrict__ cls){
    int bh = blockIdx.x;
    int b = bh >> 3, h = bh & 7;
    float* lg = g_logits + (size_t)bh * NTOK;
    __shared__ float sred[16];
    __shared__ float sbc;
    int t = threadIdx.x, lane = t & 31, warp = t >> 5;

    // cls logit (k=0): dot(u[bh], cls)/32
    {
        const float* u = g_u + (size_t)bh * D_;
        float a = 0.f;
        for (int d = t; d < D_; d += 512) a += u[d] * cls[d];
        a = warp_sum(a);
        if (lane == 0) sred[warp] = a;
        __syncthreads();
        if (t == 0){
            float s = 0.f;
            #pragma unroll
            for (int i = 0; i < 16; i++) s += sred[i];
            lg[0] = s * 0.03125f;
        }
        __syncthreads();
    }

    float mx = -INFINITY;
    for (int k = t; k < NTOK; k += 512) mx = fmaxf(mx, lg[k]);
    #pragma unroll
    for (int o = 16; o; o >>= 1) mx = fmaxf(mx, __shfl_xor_sync(0xffffffffu, mx, o));
    if (lane == 0) sred[warp] = mx;
    __syncthreads();
    if (t == 0){
        float m = sred[0];
        #pragma unroll
        for (int i = 1; i < 16; i++) m = fmaxf(m, sred[i]);
        sbc = m;
    }
    __syncthreads();
    float m = sbc;

    float sum = 0.f;
    for (int k = t; k < NTOK; k += 512){
        float e = expf(lg[k] - m);
        lg[k] = e;
        sum += e;
    }
    sum = warp_sum(sum);
    if (lane == 0) sred[warp] = sum;
    __syncthreads();
    if (t == 0){
        float s = 0.f;
        #pragma unroll
        for (int i = 0; i < 16; i++) s += sred[i];
        sbc = s;
    }
    __syncthreads();
    float inv = 1.f / sbc;
    __half* arow = g_A16 + ((size_t)b*16 + h) * 4096;
    for (int k = t; k < NTOK; k += 512){
        float v = lg[k] * inv;
        lg[k] = v;
        if (k > 0) arow[k-1] = __float2half(v);
    }
    __syncthreads();

    float a0 = lg[0];
    float* xb = g_xbar + ((size_t)b*16 + h) * D_;
    for (int d = t; d < D_; d += 512)
        xb[d] = a0 * cls[d];
}

// ---------------- 8) xbar: k-split wmma with smem-staged A tile ----------------
// grid (4 nt-groups, 16 ks-chunks, B). Block stages its 16x256 A chunk (8 valid
// rows coalesced from global, rows 8-15 zero-filled) in smem ONCE; all 8 warps
// fragment-load from smem (was: 8x redundant scattered global loads incl. zeros).
__global__ void __launch_bounds__(256) k_xbar(){
    int b    = blockIdx.z;
    int ks   = blockIdx.y;                 // 0..15, 256 tokens each
    int t    = threadIdx.x;
    int warp = t >> 5, lane = t & 31;
    int nt0  = blockIdx.x*8 + warp;        // 0..31

    __shared__ __half sA[16*256];          // 8KB: A chunk [16 headpad][256 tok]
    {
        // rows 0..7 from global (each row 256 halfs = 32 uint4), rows 8..15 zero
        int row = t >> 5, chunk = t & 31;  // 256 threads -> 8 rows x 32 chunks
        const uint4* src = (const uint4*)(g_A16 + ((size_t)b*16 + row)*4096 + ks*256);
        ((uint4*)(sA + row*256))[chunk] = src[chunk];
        ((uint4*)(sA + (row+8)*256))[chunk] = make_uint4(0,0,0,0);
    }
    __syncthreads();

    wmma::fragment<wmma::matrix_a,16,16,16,__half,wmma::row_major> fa;
    wmma::fragment<wmma::matrix_b,16,16,16,__half,wmma::row_major> fb0, fb1;
    wmma::fragment<wmma::accumulator,16,16,16,float> acc0, acc1;
    wmma::fill_fragment(acc0, 0.f);
    wmma::fill_fragment(acc1, 0.f);

    const __half* xr = g_x + ((size_t)b*N_ + ks*256) * D_;
    #pragma unroll
    for (int k = 0; k < 16; k++){
        wmma::load_matrix_sync(fa, sA + k*16, 256);
        wmma::load_matrix_sync(fb0, xr + (size_t)k*16*D_ + nt0*16, D_);
        wmma::load_matrix_sync(fb1, xr + (size_t)k*16*D_ + (nt0+32)*16, D_);
        wmma::mma_sync(acc0, fa, fb0, acc0);
        wmma::mma_sync(acc1, fa, fb1, acc1);
    }
    __shared__ float sx[8][512];
    wmma::store_matrix_sync(&sx[warp][0],   acc0, 16, wmma::mem_row_major);
    wmma::store_matrix_sync(&sx[warp][256], acc1, 16, wmma::mem_row_major);
    __syncwarp();
    #pragma unroll
    for (int e = lane; e < 128; e += 32){       // rows 0..7 only
        int r = e >> 4, c = e & 15;
        atomicAdd(&g_xbar[((size_t)b*16 + r)*D_ + nt0*16 + c],      sx[warp][r*16 + c]);
        atomicAdd(&g_xbar[((size_t)b*16 + r)*D_ + (nt0+32)*16 + c], sx[warp][256 + r*16 + c]);
    }
}

// ---------------- 9) O: block per row j; also init out[] (block 0) ----------------
__global__ void __launch_bounds__(256) k_O(const float* __restrict__ Wv, const float* __restrict__ bv,
                                           const float* __restrict__ bfc, float* __restrict__ out){
    int j = blockIdx.x, t = threadIdx.x, lane = t & 31, wp = t >> 5;
    int h = j >> 7;
    if (j == 0 && t < 16) out[t] = bfc[t & 1];
    float4 w = __ldg((const float4*)(Wv + (size_t)j * D_) + t);
    float acc[B_];
    #pragma unroll
    for (int b = 0; b < B_; b++){
        float4 v = __ldg((const float4*)(g_xbar + ((size_t)(b*16 + h))*D_) + t);
        acc[b] = w.x*v.x + w.y*v.y + w.z*v.z + w.w*v.w;
    }
    __shared__ float red[8][B_];
    #pragma unroll
    for (int b = 0; b < B_; b++) acc[b] = warp_sum(acc[b]);
    if (lane == 0){
        #pragma unroll
        for (int b = 0; b < B_; b++) red[wp][b] = acc[b];
    }
    __syncthreads();
    if (t < B_){
        float s = 0.f;
        #pragma unroll
        for (int i = 0; i < 8; i++) s += red[i][t];
        g_O[t*D_ + j] = g_Qp[t*D_ + j] + bv[j] + s;
    }
}

// ---------------- 10) O2+fc fused: out[b,c] += (O + relu(Wo.O + bo))_j * Wfc[c,j] ----------------
__global__ void __launch_bounds__(256) k_O2F(const float* __restrict__ Wo, const float* __restrict__ bo,
                                             const float* __restrict__ Wfc, float* __restrict__ out){
    int j = blockIdx.x, t = threadIdx.x, lane = t & 31, wp = t >> 5;
    float4 w = __ldg((const float4*)(Wo + (size_t)j * D_) + t);
    float acc[B_];
    #pragma unroll
    for (int b = 0; b < B_; b++){
        float4 v = __ldg((const float4*)(g_O + (size_t)b*D_) + t);
        acc[b] = w.x*v.x + w.y*v.y + w.z*v.z + w.w*v.w;
    }
    __shared__ float red[8][B_];
    #pragma unroll
    for (int b = 0; b < B_; b++) acc[b] = warp_sum(acc[b]);
    if (lane == 0){
        #pragma unroll
        for (int b = 0; b < B_; b++) red[wp][b] = acc[b];
    }
    __syncthreads();
    if (t < B_){
        float s = 0.f;
        #pragma unroll
        for (int i = 0; i < 8; i++) s += red[i][t];
        float o2 = g_O[t*D_ + j] + fmaxf(s + bo[j], 0.f);
        atomicAdd(&out[t*2 + 0], o2 * Wfc[j]);
        atomicAdd(&out[t*2 + 1], o2 * Wfc[D_ + j]);
    }
}

// ---------------- stream/event infra (created in global ctor) ----------------
static cudaStream_t s_aux;
static cudaEvent_t  ev_q, ev_conv;
namespace {
struct _FRMIL_Init {
    _FRMIL_Init(){
        cudaStreamCreateWithFlags(&s_aux, cudaStreamNonBlocking);
        cudaEventCreateWithFlags(&ev_q,    cudaEventDisableTiming);
        cudaEventCreateWithFlags(&ev_conv, cudaEventDisableTiming);
    }
} _frmil_init_;
}

// ---------------- launcher (EXACT R14 schedule) ----------------
extern "C" void kernel_launch(void* const* d_in, const int* in_sizes, int n_in,
                              void* d_out, int out_size){
    const float* inputs = (const float*)d_in[0];
    const float* Wenc   = (const float*)d_in[1];
    // d_in[2] = b_enc : constant shift through sigmoid, irrelevant for argmax
    const float* cls    = (const float*)d_in[3];
    const float* convw  = (const float*)d_in[4];
    const float* convb  = (const float*)d_in[5];
    const float* Wq     = (const float*)d_in[6];
    const float* bq     = (const float*)d_in[7];
    const float* Wk     = (const float*)d_in[8];
    // d_in[9] = bk : constant per (b,h) logit offset -> cancels in softmax
    const float* Wv     = (const float*)d_in[10];
    const float* bv     = (const float*)d_in[11];
    const float* Wo     = (const float*)d_in[12];
    const float* bo     = (const float*)d_in[13];
    const float* Wfc    = (const float*)d_in[14];
    const float* bfc    = (const float*)d_in[15];
    float* out = (float*)d_out;

    k_score<<<B_*N_/8, 256>>>(inputs, Wenc);     // score + argmax + g_u zero + Q copy
    cudaEventRecord(ev_q, 0);

    // aux: conv overlaps qp/u/u16 on main
    cudaStreamWaitEvent(s_aux, ev_q, 0);
    k_conv<<<dim3(16, 4, B_), 256, 0, s_aux>>>(inputs, convw, convb);
    cudaEventRecord(ev_conv, s_aux);

    k_qp  <<<D_, 256>>>(Wq, bq);
    k_u   <<<dim3(16, H_, 4), 256>>>(Wk);
    k_u16 <<<64, 128>>>();

    cudaStreamWaitEvent(0, ev_conv, 0);
    k_logits <<<dim3(N_/16, B_), 256>>>();
    k_softmax<<<B_*H_, 512>>>(cls);
    k_xbar   <<<dim3(4, 16, B_), 256>>>();
    k_O      <<<D_, 256>>>(Wv, bv, bfc, out);
    k_O2F    <<<D_, 256>>>(Wo, bo, Wfc, out);
}